// round 1
// baseline (speedup 1.0000x reference)
#include <cuda_runtime.h>
#include <math.h>
#include <stdint.h>

// ---------------- problem constants ----------------
#define T_STEPS 64
#define B_SZ    512
#define OBS_    1536
#define ACT_    32
#define D_      2048
#define H_      2048
#define K_      32
#define V_      32
#define S_      1024   // K_*V_

// ---------------- device scratch (no allocations allowed) ----------------
__device__ float g_obs_e[(size_t)T_STEPS * B_SZ * H_];   // 256 MB
__device__ float g_act_e[(size_t)T_STEPS * B_SZ * H_];   // 256 MB (reused for priors hidden)
__device__ float g_x[(size_t)B_SZ * H_];
__device__ float g_parts[(size_t)B_SZ * 3 * D_];
__device__ float g_h[(size_t)B_SZ * H_];
__device__ float g_deter[(size_t)B_SZ * D_];
__device__ int   g_idx[B_SZ * K_];

// ---------------- fp32 SGEMM, double-buffered, fused epilogues ----------------
// EPI: 0=none, 1=+bias, 2=+bias,ELU, 3=+bias,+addmat,ELU
template<int BM, int BN, int BK, int TM, int TN, bool CONCAT, int EPI>
__global__ void __launch_bounds__((BM/TM)*(BN/TN))
sgemm_kernel(const float* __restrict__ A, const float* __restrict__ A2,
             const float* __restrict__ B, float* __restrict__ C,
             const float* __restrict__ bias, const float* __restrict__ addm,
             int M, int N, int K, int K1)
{
    constexpr int THREADS = (BM/TM)*(BN/TN);
    static_assert(THREADS == 256, "expect 256 threads");
    constexpr int BMP = BM + 4;                  // pad keeps 16B row alignment (BMP*4 % 16 == 0)
    __shared__ __align__(16) float As[2][BK][BMP];
    __shared__ __align__(16) float Bs[2][BK][BN];

    const int tid = threadIdx.x;
    const int tx  = tid % (BN/TN);
    const int ty  = tid / (BN/TN);
    const int bm  = blockIdx.y * BM;
    const int bn  = blockIdx.x * BN;

    constexpr int A_TPR = BK / 4;                // threads per A row (float4)
    constexpr int A_RS  = THREADS / A_TPR;       // row stride
    constexpr int A_IT  = BM / A_RS;             // iterations
    const int a_r = tid / A_TPR;
    const int a_c = (tid % A_TPR) * 4;

    constexpr int B_TPR = BN / 4;
    constexpr int B_RS  = THREADS / B_TPR;
    constexpr int B_IT  = BK / B_RS;
    const int b_r = tid / B_TPR;
    const int b_c = (tid % B_TPR) * 4;

    float4 ar[A_IT];
    float4 br[B_IT];
    float acc[TM][TN];
    #pragma unroll
    for (int i = 0; i < TM; ++i)
        #pragma unroll
        for (int j = 0; j < TN; ++j) acc[i][j] = 0.f;

    auto gload = [&](int kt) {
        const int k0 = kt * BK;
        #pragma unroll
        for (int i = 0; i < A_IT; ++i) {
            int gr = bm + a_r + i * A_RS;
            int gk = k0 + a_c;
            const float* src;
            if (CONCAT) {
                src = (gk < K1) ? (A  + (size_t)gr * K1       + gk)
                                : (A2 + (size_t)gr * (K - K1) + (gk - K1));
            } else {
                src = A + (size_t)gr * K + gk;
            }
            ar[i] = *(const float4*)src;
        }
        #pragma unroll
        for (int i = 0; i < B_IT; ++i) {
            int gr = k0 + b_r + i * B_RS;
            br[i] = *(const float4*)(B + (size_t)gr * N + bn + b_c);
        }
    };
    auto sstore = [&](int bf) {
        #pragma unroll
        for (int i = 0; i < A_IT; ++i) {
            int r = a_r + i * A_RS;
            As[bf][a_c + 0][r] = ar[i].x;
            As[bf][a_c + 1][r] = ar[i].y;
            As[bf][a_c + 2][r] = ar[i].z;
            As[bf][a_c + 3][r] = ar[i].w;
        }
        #pragma unroll
        for (int i = 0; i < B_IT; ++i)
            *(float4*)(&Bs[bf][b_r + i * B_RS][b_c]) = br[i];
    };

    const int ntiles = K / BK;
    gload(0);
    sstore(0);
    __syncthreads();
    int buf = 0;
    for (int kt = 0; kt < ntiles; ++kt) {
        if (kt + 1 < ntiles) gload(kt + 1);       // global loads overlap compute below
        #pragma unroll
        for (int kk = 0; kk < BK; ++kk) {
            float a[TM], b[TN];
            #pragma unroll
            for (int i = 0; i < TM; i += 4)
                *(float4*)(a + i) = *(const float4*)(&As[buf][kk][ty * TM + i]);
            #pragma unroll
            for (int j = 0; j < TN; j += 4)
                *(float4*)(b + j) = *(const float4*)(&Bs[buf][kk][tx * TN + j]);
            #pragma unroll
            for (int i = 0; i < TM; ++i)
                #pragma unroll
                for (int j = 0; j < TN; ++j)
                    acc[i][j] = fmaf(a[i], b[j], acc[i][j]);
        }
        if (kt + 1 < ntiles) sstore(buf ^ 1);
        __syncthreads();
        buf ^= 1;
    }

    #pragma unroll
    for (int i = 0; i < TM; ++i) {
        int row = bm + ty * TM + i;
        #pragma unroll
        for (int j = 0; j < TN; ++j) {
            int col = bn + tx * TN + j;
            float v = acc[i][j];
            if (EPI >= 1) v += bias[col];
            if (EPI == 3) v += addm[(size_t)row * N + col];
            if (EPI >= 2) v = (v > 0.f) ? v : expm1f(v);   // ELU(alpha=1)
            C[(size_t)row * N + col] = v;
        }
    }
}

// ---------------- x = elu(act_e[t] + b_is + sum of one-hot-selected W_is rows) ----------------
__global__ void x_gather_kernel(const float* __restrict__ ae,
                                const float* __restrict__ b_is,
                                const float* __restrict__ W_is,
                                const int* __restrict__ idx,
                                float* __restrict__ x)
{
    int j = blockIdx.x * blockDim.x + threadIdx.x;  // column 0..H_-1
    int b = blockIdx.y;
    __shared__ int sid[K_];
    if (threadIdx.x < K_) sid[threadIdx.x] = idx[b * K_ + threadIdx.x];
    __syncthreads();
    float v = ae[(size_t)b * H_ + j] + b_is[j];
    #pragma unroll
    for (int k = 0; k < K_; ++k)
        v += W_is[(size_t)sid[k] * H_ + j];
    x[(size_t)b * H_ + j] = (v > 0.f) ? v : expm1f(v);
}

// ---------------- fused LayerNorm(6144) + GRU gates + deter update ----------------
__global__ void ln_gru_kernel(const float* __restrict__ parts,
                              const float* __restrict__ ln_g,
                              const float* __restrict__ ln_b,
                              float* __restrict__ deter,
                              float* __restrict__ deters_out)
{
    const int row = blockIdx.x;
    const float* p = parts + (size_t)row * (3 * D_);
    float s = 0.f, s2 = 0.f;
    for (int i = threadIdx.x * 4; i < 3 * D_; i += 256 * 4) {
        float4 v = *(const float4*)(p + i);
        s  += v.x + v.y + v.z + v.w;
        s2 += v.x * v.x + v.y * v.y + v.z * v.z + v.w * v.w;
    }
    __shared__ float shs[8], shs2[8];
    #pragma unroll
    for (int off = 16; off > 0; off >>= 1) {
        s  += __shfl_down_sync(0xffffffffu, s,  off);
        s2 += __shfl_down_sync(0xffffffffu, s2, off);
    }
    int warp = threadIdx.x >> 5, lane = threadIdx.x & 31;
    if (lane == 0) { shs[warp] = s; shs2[warp] = s2; }
    __syncthreads();
    __shared__ float sh_m, sh_rstd;
    if (threadIdx.x == 0) {
        float S = 0.f, S2 = 0.f;
        #pragma unroll
        for (int i = 0; i < 8; ++i) { S += shs[i]; S2 += shs2[i]; }
        float m   = S * (1.f / (3 * D_));
        float var = S2 * (1.f / (3 * D_)) - m * m;
        sh_m = m; sh_rstd = rsqrtf(var + 1e-5f);
    }
    __syncthreads();
    const float m = sh_m, rstd = sh_rstd;
    for (int j = threadIdx.x; j < D_; j += 256) {
        float r = (p[j]          - m) * rstd * ln_g[j]          + ln_b[j];
        float c = (p[j + D_]     - m) * rstd * ln_g[j + D_]     + ln_b[j + D_];
        float u = (p[j + 2 * D_] - m) * rstd * ln_g[j + 2 * D_] + ln_b[j + 2 * D_];
        float sr   = 1.f / (1.f + expf(-r));
        float cand = tanhf(sr * c);
        float up   = 1.f / (1.f + expf(-(u - 1.f)));      // update_bias = -1
        float dprev = deter[(size_t)row * D_ + j];
        float dn = up * cand + (1.f - up) * dprev;
        deter[(size_t)row * D_ + j] = dn;
        deters_out[(size_t)row * D_ + j] = dn;
    }
}

// ---------------- gumbel-max sampling: one warp per (b,k) ----------------
__global__ void sample_kernel(const float* __restrict__ logits,
                              const float* __restrict__ unif,
                              int* __restrict__ idx_out,
                              float* __restrict__ stochs_out)
{
    int gw   = (blockIdx.x * blockDim.x + threadIdx.x) >> 5;  // b*K_ + k
    int lane = threadIdx.x & 31;                               // v index
    size_t base = (size_t)gw * V_ + lane;
    float logit = logits[base];
    float u = unif[base];
    u = fminf(fmaxf(u, 1e-5f), 1.0f - 1e-5f);
    float val = logit - logf(-logf(u));
    int idx = lane;
    #pragma unroll
    for (int off = 16; off > 0; off >>= 1) {
        float ov = __shfl_down_sync(0xffffffffu, val, off);
        int   oi = __shfl_down_sync(0xffffffffu, idx, off);
        if (ov > val || (ov == val && oi < idx)) { val = ov; idx = oi; }  // first-index tiebreak
    }
    idx = __shfl_sync(0xffffffffu, idx, 0);
    stochs_out[base] = (lane == idx) ? 1.0f : 0.0f;   // sample == onehot numerically
    if (lane == 0) idx_out[gw] = ((gw & (K_ - 1)) << 5) | idx;  // absolute row in W_is
}

// ---------------- host orchestration (graph-capturable: launches + async D2D only) ----------------
extern "C" void kernel_launch(void* const* d_in, const int* in_sizes, int n_in,
                              void* d_out, int out_size)
{
    (void)in_sizes; (void)n_in; (void)out_size;
    const float* obs    = (const float*)d_in[0];
    const float* act    = (const float*)d_in[1];
    const float* deter0 = (const float*)d_in[2];
    const float* stoch0 = (const float*)d_in[3];
    const float* unif   = (const float*)d_in[4];
    const float* W_oo   = (const float*)d_in[5];
    const float* b_oo   = (const float*)d_in[6];
    const float* W_ia   = (const float*)d_in[7];
    const float* b_ia   = (const float*)d_in[8];
    const float* W_is   = (const float*)d_in[9];
    const float* b_is   = (const float*)d_in[10];
    const float* W_gru  = (const float*)d_in[11];
    const float* ln_g   = (const float*)d_in[12];
    const float* ln_b   = (const float*)d_in[13];
    const float* W_od   = (const float*)d_in[14];
    const float* b_od   = (const float*)d_in[15];
    const float* W_op   = (const float*)d_in[16];
    const float* b_op   = (const float*)d_in[17];
    const float* W_io   = (const float*)d_in[18];
    const float* b_io   = (const float*)d_in[19];
    const float* W_ip   = (const float*)d_in[20];
    const float* b_ip   = (const float*)d_in[21];

    float* out    = (float*)d_out;
    float* deters = out;
    float* stochs = deters + (size_t)T_STEPS * B_SZ * D_;
    float* posts  = stochs + (size_t)T_STEPS * B_SZ * S_;
    float* priors = posts  + (size_t)T_STEPS * B_SZ * S_;

    float *obs_e, *act_e, *xbuf, *parts, *hbuf, *deter; int* idxb;
    cudaGetSymbolAddress((void**)&obs_e, g_obs_e);
    cudaGetSymbolAddress((void**)&act_e, g_act_e);
    cudaGetSymbolAddress((void**)&xbuf,  g_x);
    cudaGetSymbolAddress((void**)&parts, g_parts);
    cudaGetSymbolAddress((void**)&hbuf,  g_h);
    cudaGetSymbolAddress((void**)&deter, g_deter);
    cudaGetSymbolAddress((void**)&idxb,  g_idx);

    cudaMemcpyAsync(deter, deter0, (size_t)B_SZ * D_ * sizeof(float),
                    cudaMemcpyDeviceToDevice, 0);

    // obs_e = obs @ W_oo + b_oo    [32768,1536]x[1536,2048]
    {
        dim3 g(H_ / 128, (T_STEPS * B_SZ) / 128);
        sgemm_kernel<128,128,16,8,8,false,1><<<g, 256>>>(
            obs, nullptr, W_oo, obs_e, b_oo, nullptr, T_STEPS * B_SZ, H_, OBS_, 0);
    }
    // act_e = act @ W_ia + b_ia    [32768,32]x[32,2048]
    {
        dim3 g(H_ / 128, (T_STEPS * B_SZ) / 128);
        sgemm_kernel<128,128,16,8,8,false,1><<<g, 256>>>(
            act, nullptr, W_ia, act_e, b_ia, nullptr, T_STEPS * B_SZ, H_, ACT_, 0);
    }

    for (int t = 0; t < T_STEPS; ++t) {
        const float* ae = act_e + (size_t)t * B_SZ * H_;
        const float* oe = obs_e + (size_t)t * B_SZ * H_;

        // x = elu(act_e[t] + stoch @ W_is + b_is)
        if (t == 0) {
            dim3 g(H_ / 128, B_SZ / 64);
            sgemm_kernel<64,128,16,4,8,false,3><<<g, 256>>>(
                stoch0, nullptr, W_is, xbuf, b_is, ae, B_SZ, H_, S_, 0);
        } else {
            dim3 g(H_ / 256, B_SZ);
            x_gather_kernel<<<g, 256>>>(ae, b_is, W_is, idxb, xbuf);
        }
        // parts = [x | deter] @ W_gru    [512,4096]x[4096,6144]
        {
            dim3 g((3 * D_) / 128, B_SZ / 128);
            sgemm_kernel<128,128,16,8,8,true,0><<<g, 256>>>(
                xbuf, deter, W_gru, parts, nullptr, nullptr, B_SZ, 3 * D_, H_ + D_, H_);
        }
        // layernorm + gates + deter update (writes deters[t])
        ln_gru_kernel<<<B_SZ, 256>>>(parts, ln_g, ln_b, deter,
                                     deters + (size_t)t * B_SZ * D_);
        // h = elu(deter @ W_od + b_od + obs_e[t])
        {
            dim3 g(H_ / 128, B_SZ / 64);
            sgemm_kernel<64,128,16,4,8,false,3><<<g, 256>>>(
                deter, nullptr, W_od, hbuf, b_od, oe, B_SZ, H_, D_, 0);
        }
        // posts[t] = h @ W_op + b_op
        {
            dim3 g(S_ / 64, B_SZ / 64);
            sgemm_kernel<64,64,16,4,4,false,1><<<g, 256>>>(
                hbuf, nullptr, W_op, posts + (size_t)t * B_SZ * S_, b_op, nullptr,
                B_SZ, S_, H_, 0);
        }
        // gumbel-max sample -> stochs[t], indices for next step's gather
        sample_kernel<<<(B_SZ * K_ * 32) / 256, 256>>>(
            posts + (size_t)t * B_SZ * S_,
            unif + (size_t)t * B_SZ * K_ * V_,
            idxb,
            stochs + (size_t)t * B_SZ * S_);
    }

    // priors = (elu(deters @ W_io + b_io)) @ W_ip + b_ip
    {
        dim3 g(H_ / 128, (T_STEPS * B_SZ) / 128);
        sgemm_kernel<128,128,16,8,8,false,2><<<g, 256>>>(
            deters, nullptr, W_io, act_e /*reuse as scratch*/, b_io, nullptr,
            T_STEPS * B_SZ, H_, D_, 0);
    }
    {
        dim3 g(S_ / 128, (T_STEPS * B_SZ) / 128);
        sgemm_kernel<128,128,16,8,8,false,1><<<g, 256>>>(
            act_e, nullptr, W_ip, priors, b_ip, nullptr, T_STEPS * B_SZ, S_, H_, 0);
    }
}